// round 11
// baseline (speedup 1.0000x reference)
#include <cuda_runtime.h>

// DigitCaps dynamic routing, fused. B=64, R=6912, I=8, C=10, O=16, 3 iters.
//
// Register-resident W: warp = 16 r-lanes x 2 o-halves. Lane holds W[r][8i][8o]
// (64 floats = 32 regs) loaded once per tile from XOR-swizzled smem with
// conflict-free UNIQUE-data LDS. The b-loop (64 iters) reads x from its native
// [b][r][i] layout (coalesced, L2-hot, depth-2 prefetch) — no transpose kernel.
// Cross-r fold: split-exchange shfl butterfly (8 SHFLs fold 8 values over 16 lanes).
//   k_pass<0>: p=W^T x; acc += p;                 last CTA: out0=squash
//   k_pass<1>: w=exp(p.out0); acc += w*p;         last CTA: ovsum=out0+squash
//   k_pass<2>: w=exp(p.ovsum); acc += w*p;        last CTA: squash->d_out
// Replay-clean: last CTA of each pass zeroes accumulators + resets counter.

#define R_DIM 6912
#define B_DIM 64
#define C_DIM 10
#define R_BLK 128
#define NCTAS ((R_DIM / R_BLK) * C_DIM)   // 540
#define SMEM_DYN 65536

typedef unsigned long long u64;

__device__ __align__(16) float g_acc[C_DIM * B_DIM * 16];
__device__ __align__(16) float g_accw[C_DIM * B_DIM];
__device__ __align__(16) float g_out0[C_DIM * B_DIM * 16];
__device__ __align__(16) float g_ovsum[C_DIM * B_DIM * 16];
__device__ unsigned g_ctr = 0;

__device__ __forceinline__ u64 pack2(float lo, float hi) {
    u64 r; asm("mov.b64 %0, {%1, %2};" : "=l"(r) : "f"(lo), "f"(hi)); return r;
}
__device__ __forceinline__ void unpack2(u64 v, float& lo, float& hi) {
    asm("mov.b64 {%0, %1}, %2;" : "=f"(lo), "=f"(hi) : "l"(v));
}
__device__ __forceinline__ u64 fma2(u64 a, u64 b, u64 c) {
    u64 d; asm("fma.rn.f32x2 %0, %1, %2, %3;" : "=l"(d) : "l"(a), "l"(b), "l"(c)); return d;
}
__device__ __forceinline__ u64 mul2(u64 a, u64 b) {
    u64 d; asm("mul.rn.f32x2 %0, %1, %2;" : "=l"(d) : "l"(a), "l"(b)); return d;
}
__device__ __forceinline__ unsigned smem_u32(const void* p) {
    return (unsigned)__cvta_generic_to_shared(p);
}
__device__ __forceinline__ void cp_async16(unsigned saddr, const void* g) {
    asm volatile("cp.async.cg.shared.global [%0], [%1], 16;" :: "r"(saddr), "l"(g));
}

// MODE 0: uniform; 1: w=exp(p.out0); 2: w=exp(p.ovsum)
template <int MODE>
__global__ void __launch_bounds__(256, 2)
k_pass(const float* __restrict__ xg, const float* __restrict__ Wg,
       float* __restrict__ dout) {
    extern __shared__ __align__(16) char smem[];
    float* sW   = reinterpret_cast<float*>(smem);     // 64 KB staging (aliased below)
    float* sacc = reinterpret_cast<float*>(smem);     // [8 warps][64 b][16 o] = 32 KB
    __shared__ float saccw[8 * B_DIM];
    __shared__ unsigned s_rank;

    const int c      = blockIdx.y;
    const int rblock = blockIdx.x * R_BLK;
    const int tid    = threadIdx.x;
    const int w      = tid >> 5;
    const int lane   = tid & 31;
    const int oh     = lane >> 4;                 // o-half 0/1
    const int rl     = lane & 15;                 // lane's r within warp
    const int rloc   = w * 16 + rl;               // CTA-local r (0..127)

    // ---- stage W chunk (128 r x 512 B = 64 KB), XOR-swizzled 16B granules ----
    {
        const char* src = reinterpret_cast<const char*>(
            Wg + ((size_t)c * R_DIM + rblock) * 128);
        unsigned dstb = smem_u32(sW);
        #pragma unroll
        for (int s = 0; s < 16; s++) {
            int gid = tid + s * 256;              // 4096 granules of 16 B
            int r = gid >> 5, g = gid & 31;
            cp_async16(dstb + (unsigned)((r * 32 + (g ^ (r & 7))) * 16),
                       src + (size_t)gid * 16);
        }
        asm volatile("cp.async.commit_group;");
    }
    asm volatile("cp.async.wait_group 0;");
    __syncthreads();

    // ---- load lane's W slice into registers: 16 conflict-free LDS.128 ----
    ulonglong2 wreg[8][2];
    {
        unsigned base = smem_u32(sW);
        #pragma unroll
        for (int i = 0; i < 8; i++)
            #pragma unroll
            for (int j = 0; j < 2; j++) {
                int g = i * 4 + oh * 2 + j;
                unsigned a = base + (unsigned)((rloc * 32 + (g ^ (rl & 7))) * 16);
                asm volatile("ld.shared.v2.u64 {%0, %1}, [%2];"
                             : "=l"(wreg[i][j].x), "=l"(wreg[i][j].y) : "r"(a));
            }
    }
    __syncthreads();   // all sW reads done -> sacc aliasing safe

    const float4* xl = reinterpret_cast<const float4*>(xg)
                     + (size_t)(rblock + rloc) * 2;        // x[b][r][i]: +b*13824
    const float* ovsrc = (MODE == 1) ? (g_out0 + c * (B_DIM * 16))
                                     : (g_ovsum + c * (B_DIM * 16));

    // output o index for this lane's butterfly result (even rl lanes write)
    const int o_out = oh * 8 + ((rl >> 3) & 1) * 4 + ((rl >> 2) & 1) * 2 + ((rl >> 1) & 1);

    // depth-2 x prefetch
    float4 xA[2], xB[2];
    xA[0] = xl[0];      xB[0] = xl[1];
    xA[1] = xl[13824];  xB[1] = xl[13824 + 1];

    #pragma unroll 2
    for (int b = 0; b < B_DIM; b++) {
        float4 xa = xA[b & 1], xbv = xB[b & 1];
        {
            int bn = (b + 2) & 63;                 // wraps harmlessly at the end
            xA[b & 1] = xl[(size_t)bn * 13824];
            xB[b & 1] = xl[(size_t)bn * 13824 + 1];
        }
        const float xf[8] = {xa.x, xa.y, xa.z, xa.w, xbv.x, xbv.y, xbv.z, xbv.w};

        u64 ovv[4];
        if (MODE != 0) {
            const ulonglong2* op = reinterpret_cast<const ulonglong2*>(
                ovsrc + b * 16 + oh * 8);
            ulonglong2 o0 = op[0], o1 = op[1];
            ovv[0] = o0.x; ovv[1] = o0.y; ovv[2] = o1.x; ovv[3] = o1.y;
        }

        u64 p[4] = {0ull, 0ull, 0ull, 0ull};       // lane's 8 o accumulators
        #pragma unroll
        for (int i = 0; i < 8; i++) {
            u64 xx = pack2(xf[i], xf[i]);
            p[0] = fma2(wreg[i][0].x, xx, p[0]);
            p[1] = fma2(wreg[i][0].y, xx, p[1]);
            p[2] = fma2(wreg[i][1].x, xx, p[2]);
            p[3] = fma2(wreg[i][1].y, xx, p[3]);
        }

        float f[8];
        float sw = 0.0f;
        if (MODE == 0) {
            #pragma unroll
            for (int t = 0; t < 4; t++) unpack2(p[t], f[2 * t], f[2 * t + 1]);
        } else {
            u64 d = 0ull;
            #pragma unroll
            for (int t = 0; t < 4; t++) d = fma2(p[t], ovv[t], d);
            float lo, hi; unpack2(d, lo, hi);
            float del = lo + hi;
            del += __shfl_xor_sync(0xffffffffu, del, 16);   // join o-halves (same r)
            del = fminf(del, 70.0f);
            float wgt = __expf(del);
            u64 w2 = pack2(wgt, wgt);
            #pragma unroll
            for (int t = 0; t < 4; t++) {
                u64 q = mul2(p[t], w2);
                unpack2(q, f[2 * t], f[2 * t + 1]);
            }
            sw = wgt;
        }

        // ---- split-exchange butterfly over the 16 r-lanes (per o-half) ----
        {   // stage 1 (xor 8): 8 -> 4 live values
            const bool hi = (rl & 8) != 0;
            float s0 = hi ? f[0] : f[4], s1 = hi ? f[1] : f[5];
            float s2 = hi ? f[2] : f[6], s3 = hi ? f[3] : f[7];
            float r0 = __shfl_xor_sync(0xffffffffu, s0, 8);
            float r1 = __shfl_xor_sync(0xffffffffu, s1, 8);
            float r2 = __shfl_xor_sync(0xffffffffu, s2, 8);
            float r3 = __shfl_xor_sync(0xffffffffu, s3, 8);
            f[0] = (hi ? f[4] : f[0]) + r0;
            f[1] = (hi ? f[5] : f[1]) + r1;
            f[2] = (hi ? f[6] : f[2]) + r2;
            f[3] = (hi ? f[7] : f[3]) + r3;
        }
        {   // stage 2 (xor 4): 4 -> 2
            const bool hi = (rl & 4) != 0;
            float s0 = hi ? f[0] : f[2], s1 = hi ? f[1] : f[3];
            float r0 = __shfl_xor_sync(0xffffffffu, s0, 4);
            float r1 = __shfl_xor_sync(0xffffffffu, s1, 4);
            f[0] = (hi ? f[2] : f[0]) + r0;
            f[1] = (hi ? f[3] : f[1]) + r1;
        }
        {   // stage 3 (xor 2): 2 -> 1
            const bool hi = (rl & 2) != 0;
            float s0 = hi ? f[0] : f[1];
            float r0 = __shfl_xor_sync(0xffffffffu, s0, 2);
            f[0] = (hi ? f[1] : f[0]) + r0;
        }
        // stage 4 (xor 1): finish the 16-lane sum
        f[0] += __shfl_xor_sync(0xffffffffu, f[0], 1);

        if (!(rl & 1)) sacc[(w * B_DIM + b) * 16 + o_out] = f[0];

        if (MODE != 0) {
            sw += __shfl_xor_sync(0xffffffffu, sw, 8);
            sw += __shfl_xor_sync(0xffffffffu, sw, 4);
            sw += __shfl_xor_sync(0xffffffffu, sw, 2);
            sw += __shfl_xor_sync(0xffffffffu, sw, 1);
            if (lane == 0) saccw[w * B_DIM + b] = sw;
        }
    }
    __syncthreads();

    // ---- fold 8 warps -> global atomics ----
    for (int idx = tid; idx < B_DIM * 16; idx += 256) {
        float v = 0.0f;
        #pragma unroll
        for (int ww = 0; ww < 8; ww++) v += sacc[ww * (B_DIM * 16) + idx];
        atomicAdd(&g_acc[c * (B_DIM * 16) + idx], v);
    }
    if (MODE != 0 && tid < B_DIM) {
        float v = 0.0f;
        #pragma unroll
        for (int ww = 0; ww < 8; ww++) v += saccw[ww * B_DIM + tid];
        atomicAdd(&g_accw[c * B_DIM + tid], v);
    }

    // ---- last CTA of this pass: squash inline ----
    __threadfence();
    if (tid == 0) s_rank = atomicAdd(&g_ctr, 1);
    __syncthreads();
    if (s_rank == NCTAS - 1) {
        for (int pair = tid; pair < C_DIM * B_DIM; pair += 256) {
            const float* a = g_acc + pair * 16;
            float invw = (MODE == 0) ? (1.0f / (float)R_DIM) : (1.0f / __ldcg(&g_accw[pair]));
            float s[16], sq = 0.0f;
            #pragma unroll
            for (int o = 0; o < 16; o++) { s[o] = __ldcg(a + o) * invw; sq += s[o] * s[o]; }
            float coef = sq / ((1.0f + sq) * sqrtf(sq));
            if (MODE == 0) {
                #pragma unroll
                for (int o = 0; o < 16; o++) g_out0[pair * 16 + o] = coef * s[o];
            } else if (MODE == 1) {
                #pragma unroll
                for (int o = 0; o < 16; o++)
                    g_ovsum[pair * 16 + o] = g_out0[pair * 16 + o] + coef * s[o];
            } else {
                #pragma unroll
                for (int o = 0; o < 16; o++) dout[pair * 16 + o] = coef * s[o];
            }
        }
        __syncthreads();
        for (int idx = tid; idx < C_DIM * B_DIM * 16; idx += 256) g_acc[idx] = 0.0f;
        for (int idx = tid; idx < C_DIM * B_DIM; idx += 256) g_accw[idx] = 0.0f;
        if (tid == 0) g_ctr = 0;
    }
}

extern "C" void kernel_launch(void* const* d_in, const int* in_sizes, int n_in,
                              void* d_out, int out_size) {
    const float* x = (const float*)d_in[0];          // [64, 6912, 8]
    const float* W = (const float*)d_in[1];          // [10, 6912, 8, 16]
    float* out = (float*)d_out;                      // [10, 64, 1, 1, 16]

    cudaFuncSetAttribute(k_pass<0>, cudaFuncAttributeMaxDynamicSharedMemorySize, SMEM_DYN);
    cudaFuncSetAttribute(k_pass<1>, cudaFuncAttributeMaxDynamicSharedMemorySize, SMEM_DYN);
    cudaFuncSetAttribute(k_pass<2>, cudaFuncAttributeMaxDynamicSharedMemorySize, SMEM_DYN);

    dim3 grid(R_DIM / R_BLK, C_DIM);                 // (54, 10)
    k_pass<0><<<grid, 256, SMEM_DYN>>>(x, W, nullptr);
    k_pass<1><<<grid, 256, SMEM_DYN>>>(x, W, nullptr);
    k_pass<2><<<grid, 256, SMEM_DYN>>>(x, W, out);
}